// round 3
// baseline (speedup 1.0000x reference)
#include <cuda_runtime.h>
#include <cuda_fp16.h>

// Problem constants (B=2, C=128, H=800, W=640, N=10000)
#define BB 2
#define CC 128
#define HH 800
#define WW 640
#define NN 10000
#define HW (HH * WW)      // 512000
#define NO 16             // projected outputs = conv rows 2..17 (rows 0,1 are zeroed)

// Scratch
__device__ __half g_himg[(size_t)BB * HW * CC];   // NHWC fp16 image, 262 MB
__device__ float  g_pimg[(size_t)BB * HW * NO];   // per-pixel W[2:18]*img, fp32, 65.5 MB

#define FMA2(a, v, w)  asm("fma.rn.f32x2 %0, %1, %2, %0;" : "+l"(a) : "l"(v), "l"(w))
#define PACK2(u, x, y) asm("mov.b64 %0, {%1, %2};" : "=l"(u) : "f"(x), "f"(y))
#define UNPACK2(x, y, u) asm("mov.b64 {%0, %1}, %2;" : "=f"(x), "=f"(y) : "l"(u))

// ---------------------------------------------------------------------------
// k_prep: per block: 32 pixels x 128 channels.
//  - stage tile in smem (read img coalesced once)
//  - write fp16 NHWC copy
//  - project to 16 channels (bilinear commutes with linear proj) via f32x2 FMA
// ---------------------------------------------------------------------------
__global__ void __launch_bounds__(128) k_prep(const float* __restrict__ img,
                                              const float* __restrict__ cw)
{
    __shared__ float tile[CC][36];                     // [c][px], pad 36 (16B-aligned rows)
    __shared__ unsigned long long w2s[CC][NO];         // packed {w,w} f32x2
    __shared__ float red[4][32][NO];                   // cg partials

    const int tid = threadIdx.x;
    const int b   = blockIdx.y;
    const int hw0 = blockIdx.x * 32;

    // pack W rows 2..17 as {w,w}
    for (int i = tid; i < CC * NO; i += 128) {
        const int c = i >> 4, o = i & 15;
        const float w = cw[(o + 2) * CC + c];
        unsigned long long u; PACK2(u, w, w);
        w2s[c][o] = u;
    }

    // load tile: warp-coalesced rows of img
    {
        const int tx = tid & 31, ty = tid >> 5;
        const float* src = img + (size_t)b * CC * HW + hw0 + tx;
        #pragma unroll 8
        for (int i = 0; i < 32; i++) {
            const int c = i * 4 + ty;
            tile[c][tx] = src[(size_t)c * HW];
        }
    }
    __syncthreads();

    // projection: thread = (og 0..3, pxg 0..7, cg 0..3); 4 outs x 4 px register tile
    {
        const int og = tid & 3, pxg = (tid >> 2) & 7, cg = tid >> 5;
        unsigned long long a[8];
        #pragma unroll
        for (int j = 0; j < 8; j++) a[j] = 0ull;
        #pragma unroll 8
        for (int k = 0; k < 32; k++) {
            const int c = cg * 32 + k;
            const float4 v = *reinterpret_cast<const float4*>(&tile[c][pxg * 4]);
            unsigned long long v01, v23;
            PACK2(v01, v.x, v.y);
            PACK2(v23, v.z, v.w);
            const ulonglong2* wp = reinterpret_cast<const ulonglong2*>(&w2s[c][og * 4]);
            const ulonglong2 wa = wp[0];
            const ulonglong2 wb = wp[1];
            FMA2(a[0], v01, wa.x); FMA2(a[1], v23, wa.x);   // o = og*4+0
            FMA2(a[2], v01, wa.y); FMA2(a[3], v23, wa.y);   // o = og*4+1
            FMA2(a[4], v01, wb.x); FMA2(a[5], v23, wb.x);   // o = og*4+2
            FMA2(a[6], v01, wb.y); FMA2(a[7], v23, wb.y);   // o = og*4+3
        }
        #pragma unroll
        for (int j = 0; j < 4; j++) {
            #pragma unroll
            for (int pr = 0; pr < 2; pr++) {
                float lo, hi;
                UNPACK2(lo, hi, a[j * 2 + pr]);
                red[cg][pxg * 4 + pr * 2 + 0][og * 4 + j] = lo;
                red[cg][pxg * 4 + pr * 2 + 1][og * 4 + j] = hi;
            }
        }
    }
    __syncthreads();

    // fp16 NHWC writeout: 512 uint4 (16B) stores, perfectly coalesced
    #pragma unroll
    for (int it = 0; it < 4; it++) {
        const int idx = it * 128 + tid;
        const int px = idx >> 4, j = idx & 15;
        const int c0 = j * 8;
        uint4 u;
        __half2 h;
        h = __float22half2_rn(make_float2(tile[c0 + 0][px], tile[c0 + 1][px]));
        u.x = *reinterpret_cast<unsigned int*>(&h);
        h = __float22half2_rn(make_float2(tile[c0 + 2][px], tile[c0 + 3][px]));
        u.y = *reinterpret_cast<unsigned int*>(&h);
        h = __float22half2_rn(make_float2(tile[c0 + 4][px], tile[c0 + 5][px]));
        u.z = *reinterpret_cast<unsigned int*>(&h);
        h = __float22half2_rn(make_float2(tile[c0 + 6][px], tile[c0 + 7][px]));
        u.w = *reinterpret_cast<unsigned int*>(&h);
        *reinterpret_cast<uint4*>(g_himg + (size_t)(b * HW + hw0 + px) * CC + c0) = u;
    }

    // pimg writeout: sum 4 cg partials, float4 per thread, coalesced
    {
        const int px = tid >> 2, oq = tid & 3;
        const float4* r0 = reinterpret_cast<const float4*>(&red[0][px][0]);
        const float4* r1 = reinterpret_cast<const float4*>(&red[1][px][0]);
        const float4* r2 = reinterpret_cast<const float4*>(&red[2][px][0]);
        const float4* r3 = reinterpret_cast<const float4*>(&red[3][px][0]);
        const float4 a = r0[oq], bq = r1[oq], cq = r2[oq], dq = r3[oq];
        float4 s;
        s.x = a.x + bq.x + cq.x + dq.x;
        s.y = a.y + bq.y + cq.y + dq.y;
        s.z = a.z + bq.z + cq.z + dq.z;
        s.w = a.w + bq.w + cq.w + dq.w;
        *reinterpret_cast<float4*>(g_pimg + (size_t)(b * HW + hw0 + px) * NO + oq * 4) = s;
    }
}

// ---------------------------------------------------------------------------
// k_sample: one block per point.
//  Phase A: deltas from 4-tap bilinear of pimg (exact fp32 path)
//  Phase B: 9 locations x 4 taps from fp16 NHWC, vectorized LDG.64, one
//           float4 store per 4 channels.
// ---------------------------------------------------------------------------
__global__ void __launch_bounds__(128) k_sample(
    const float* __restrict__ verts,
    const float* __restrict__ cb,
    float* __restrict__ out)
{
    const int p = blockIdx.x;            // 0 .. B*N-1
    const int b = p / NN;
    const int tid = threadIdx.x;

    __shared__ float sd[NO];
    __shared__ int   soff[9][4];
    __shared__ float swt[9][4];

    const float vx = verts[p * 2 + 0];
    const float vy = verts[p * 2 + 1];

    const float gx = fminf(fmaxf((vx + 1.0f) * 0.5f * (WW - 1), 0.0f), (float)(WW - 1));
    const float gy = fminf(fmaxf((vy + 1.0f) * 0.5f * (HH - 1), 0.0f), (float)(HH - 1));
    const int x0 = (int)floorf(gx), y0 = (int)floorf(gy);
    const int x1 = min(x0 + 1, WW - 1), y1 = min(y0 + 1, HH - 1);
    const float wx1 = gx - (float)x0, wy1 = gy - (float)y0;
    const float wx0 = 1.0f - wx1, wy0 = 1.0f - wy1;

    // Phase A: deltas (16 threads, 4 taps each from pimg)
    if (tid < NO) {
        const float* pb = g_pimg + (size_t)b * HW * NO;
        float a = cb[tid + 2];
        a = fmaf(wy0 * wx0, pb[(size_t)(y0 * WW + x0) * NO + tid], a);
        a = fmaf(wy0 * wx1, pb[(size_t)(y0 * WW + x1) * NO + tid], a);
        a = fmaf(wy1 * wx0, pb[(size_t)(y1 * WW + x0) * NO + tid], a);
        a = fmaf(wy1 * wx1, pb[(size_t)(y1 * WW + x1) * NO + tid], a);
        sd[tid] = a;
    }
    __syncthreads();

    // 9 locations (0 = center, 1..8 = learnt neighbors) -> tap offsets + weights
    if (tid < 9) {
        float nx = vx, ny = vy;
        if (tid > 0) { nx += sd[2 * tid - 2]; ny += sd[2 * tid - 1]; }
        const float ggx = fminf(fmaxf((nx + 1.0f) * 0.5f * (WW - 1), 0.0f), (float)(WW - 1));
        const float ggy = fminf(fmaxf((ny + 1.0f) * 0.5f * (HH - 1), 0.0f), (float)(HH - 1));
        const int nx0 = (int)floorf(ggx), ny0 = (int)floorf(ggy);
        const int nx1 = min(nx0 + 1, WW - 1), ny1 = min(ny0 + 1, HH - 1);
        const float nwx1 = ggx - (float)nx0, nwy1 = ggy - (float)ny0;
        const float nwx0 = 1.0f - nwx1, nwy0 = 1.0f - nwy1;
        soff[tid][0] = (ny0 * WW + nx0) * CC;
        soff[tid][1] = (ny0 * WW + nx1) * CC;
        soff[tid][2] = (ny1 * WW + nx0) * CC;
        soff[tid][3] = (ny1 * WW + nx1) * CC;
        const float s = 1.0f / 9.0f;
        swt[tid][0] = nwy0 * nwx0 * s;
        swt[tid][1] = nwy0 * nwx1 * s;
        swt[tid][2] = nwy1 * nwx0 * s;
        swt[tid][3] = nwy1 * nwx1 * s;
    }
    __syncthreads();

    // Phase B: grp g handles tap j=g of all 9 locations; lane owns 4 channels
    const int lane = tid & 31, grp = tid >> 5;
    const __half* hb = g_himg + (size_t)b * HW * CC + lane * 4;

    float ax = 0.f, ay = 0.f, az = 0.f, aw = 0.f;
    #pragma unroll
    for (int i = 0; i < 9; i++) {
        const int off = soff[i][grp];
        const float w = swt[i][grp];
        const uint2 u = *reinterpret_cast<const uint2*>(hb + off);
        const float2 f0 = __half22float2(*reinterpret_cast<const __half2*>(&u.x));
        const float2 f1 = __half22float2(*reinterpret_cast<const __half2*>(&u.y));
        ax = fmaf(w, f0.x, ax); ay = fmaf(w, f0.y, ay);
        az = fmaf(w, f1.x, az); aw = fmaf(w, f1.y, aw);
    }

    __shared__ float4 red[4][32];
    red[grp][lane] = make_float4(ax, ay, az, aw);
    __syncthreads();

    if (tid < 32) {
        const float4 r0 = red[0][tid], r1 = red[1][tid];
        const float4 r2 = red[2][tid], r3 = red[3][tid];
        float4 o4;
        o4.x = r0.x + r1.x + r2.x + r3.x;
        o4.y = r0.y + r1.y + r2.y + r3.y;
        o4.z = r0.z + r1.z + r2.z + r3.z;
        o4.w = r0.w + r1.w + r2.w + r3.w;
        reinterpret_cast<float4*>(out)[(size_t)p * 32 + tid] = o4;
    }
}

extern "C" void kernel_launch(void* const* d_in, const int* in_sizes, int n_in,
                              void* d_out, int out_size)
{
    const float* img   = (const float*)d_in[0];   // (B, C, H, W)
    const float* verts = (const float*)d_in[1];   // (B, N, 2)
    const float* cw    = (const float*)d_in[2];   // (18, C)
    const float* cb    = (const float*)d_in[3];   // (18,)
    float* out = (float*)d_out;                   // (B, N, C)

    dim3 pgrid(HW / 32, BB);
    k_prep<<<pgrid, 128>>>(img, cw);
    k_sample<<<BB * NN, 128>>>(verts, cb, out);
}

// round 4
// speedup vs baseline: 2.7554x; 2.7554x over previous
#include <cuda_runtime.h>
#include <cuda_fp16.h>

// Problem constants (B=2, C=128, H=800, W=640, N=10000)
#define BB 2
#define CC 128
#define HH 800
#define WW 640
#define NN 10000
#define HW (HH * WW)      // 512000

// Scratch: NHWC fp16 copy of the image (value path only; delta path stays fp32)
__device__ __half g_himg[(size_t)BB * HW * CC];   // 262 MB

__device__ __forceinline__ float clampf(float v, float lo, float hi) {
    return fminf(fmaxf(v, lo), hi);
}

// ---------------------------------------------------------------------------
// k_half: transpose (B,C,H,W) fp32 -> (B,H,W,C) fp16. 32x32 tiles via smem.
// grid = (HW/32, C/32, B), block = (32, 8)
// ---------------------------------------------------------------------------
__global__ void __launch_bounds__(256) k_half(const float* __restrict__ img)
{
    __shared__ float tile[32][33];
    const int b   = blockIdx.z;
    const int c0  = blockIdx.y * 32;
    const int hw0 = blockIdx.x * 32;
    const int tx = threadIdx.x, ty = threadIdx.y;

    const float* __restrict__ src = img + ((size_t)b * CC + c0) * HW + hw0;
    #pragma unroll
    for (int j = 0; j < 32; j += 8)
        tile[ty + j][tx] = src[(size_t)(ty + j) * HW + tx];
    __syncthreads();

    __half* __restrict__ dst = g_himg + ((size_t)b * HW + hw0) * CC + c0;
    #pragma unroll
    for (int j = 0; j < 32; j += 8)
        dst[(size_t)(ty + j) * CC + tx] = __float2half(tile[tx][ty + j]);
}

// ---------------------------------------------------------------------------
// k_sample: one block per point (128 threads).
//  A) center 128-ch bilinear sample from ORIGINAL fp32 NCHW img (exact)
//  B) 16-thread dot with conv rows 2..17 -> deltas (fp32 end to end)
//  C) 9 locations -> tap offsets + weights
//  D) 36 fp16 taps (LDG.64 per 4 channels), mean, float4 coalesced store
// ---------------------------------------------------------------------------
__global__ void __launch_bounds__(128) k_sample(
    const float* __restrict__ img,
    const float* __restrict__ verts,
    const float* __restrict__ cw,
    const float* __restrict__ cb,
    float* __restrict__ out)
{
    const int p = blockIdx.x;            // 0 .. B*N-1
    const int b = p / NN;
    const int tid = threadIdx.x;

    __shared__ float sf[CC];
    __shared__ float sd[16];
    __shared__ int   soff[9][4];
    __shared__ float swt[9][4];

    const float vx = verts[p * 2 + 0];
    const float vy = verts[p * 2 + 1];

    const float gx = clampf((vx + 1.0f) * 0.5f * (WW - 1), 0.0f, (float)(WW - 1));
    const float gy = clampf((vy + 1.0f) * 0.5f * (HH - 1), 0.0f, (float)(HH - 1));
    const int x0 = (int)floorf(gx), y0 = (int)floorf(gy);
    const int x1 = min(x0 + 1, WW - 1), y1 = min(y0 + 1, HH - 1);
    const float wx1 = gx - (float)x0, wy1 = gy - (float)y0;
    const float wx0 = 1.0f - wx1, wy0 = 1.0f - wy1;

    // ---- A: center feature, exact fp32 from NCHW ----
    {
        const int c = tid;
        const float* __restrict__ ip = img + ((size_t)b * CC + c) * HW;
        const int r0 = y0 * WW, r1 = y1 * WW;
        const float v00 = __ldg(ip + r0 + x0);
        const float v01 = __ldg(ip + r0 + x1);
        const float v10 = __ldg(ip + r1 + x0);
        const float v11 = __ldg(ip + r1 + x1);
        sf[c] = v00 * (wy0 * wx0) + v01 * (wy0 * wx1)
              + v10 * (wy1 * wx0) + v11 * (wy1 * wx1);
    }
    __syncthreads();

    // ---- B: deltas = conv rows 2..17 dot center feature ----
    if (tid < 16) {
        float acc = cb[tid + 2];
        const float* __restrict__ w = cw + (tid + 2) * CC;
        #pragma unroll 8
        for (int i = 0; i < CC; i++) acc = fmaf(sf[i], w[i], acc);
        sd[tid] = acc;
    }
    __syncthreads();

    // ---- C: 9 locations (0 = center, 1..8 = learnt neighbors) ----
    if (tid < 9) {
        float nx = vx, ny = vy;
        if (tid > 0) { nx += sd[2 * tid - 2]; ny += sd[2 * tid - 1]; }
        const float ggx = clampf((nx + 1.0f) * 0.5f * (WW - 1), 0.0f, (float)(WW - 1));
        const float ggy = clampf((ny + 1.0f) * 0.5f * (HH - 1), 0.0f, (float)(HH - 1));
        const int nx0 = (int)floorf(ggx), ny0 = (int)floorf(ggy);
        const int nx1 = min(nx0 + 1, WW - 1), ny1 = min(ny0 + 1, HH - 1);
        const float nwx1 = ggx - (float)nx0, nwy1 = ggy - (float)ny0;
        const float nwx0 = 1.0f - nwx1, nwy0 = 1.0f - nwy1;
        soff[tid][0] = (ny0 * WW + nx0) * CC;
        soff[tid][1] = (ny0 * WW + nx1) * CC;
        soff[tid][2] = (ny1 * WW + nx0) * CC;
        soff[tid][3] = (ny1 * WW + nx1) * CC;
        const float s = 1.0f / 9.0f;
        swt[tid][0] = nwy0 * nwx0 * s;
        swt[tid][1] = nwy0 * nwx1 * s;
        swt[tid][2] = nwy1 * nwx0 * s;
        swt[tid][3] = nwy1 * nwx1 * s;
    }
    __syncthreads();

    // ---- D: 36 fp16 taps; grp g = tap j of all 9 locations; lane = 4 channels
    const int lane = tid & 31, grp = tid >> 5;
    const __half* hb = g_himg + (size_t)b * HW * CC + lane * 4;

    float ax = 0.f, ay = 0.f, az = 0.f, aw = 0.f;
    #pragma unroll
    for (int i = 0; i < 9; i++) {
        const int off = soff[i][grp];
        const float w = swt[i][grp];
        const uint2 u = *reinterpret_cast<const uint2*>(hb + off);
        const float2 f0 = __half22float2(*reinterpret_cast<const __half2*>(&u.x));
        const float2 f1 = __half22float2(*reinterpret_cast<const __half2*>(&u.y));
        ax = fmaf(w, f0.x, ax); ay = fmaf(w, f0.y, ay);
        az = fmaf(w, f1.x, az); aw = fmaf(w, f1.y, aw);
    }

    __shared__ float4 red[4][32];
    red[grp][lane] = make_float4(ax, ay, az, aw);
    __syncthreads();

    if (tid < 32) {
        const float4 r0 = red[0][tid], r1 = red[1][tid];
        const float4 r2 = red[2][tid], r3 = red[3][tid];
        float4 o4;
        o4.x = r0.x + r1.x + r2.x + r3.x;
        o4.y = r0.y + r1.y + r2.y + r3.y;
        o4.z = r0.z + r1.z + r2.z + r3.z;
        o4.w = r0.w + r1.w + r2.w + r3.w;
        reinterpret_cast<float4*>(out)[(size_t)p * 32 + tid] = o4;
    }
}

extern "C" void kernel_launch(void* const* d_in, const int* in_sizes, int n_in,
                              void* d_out, int out_size)
{
    const float* img   = (const float*)d_in[0];   // (B, C, H, W)
    const float* verts = (const float*)d_in[1];   // (B, N, 2)
    const float* cw    = (const float*)d_in[2];   // (18, C)
    const float* cb    = (const float*)d_in[3];   // (18,)
    float* out = (float*)d_out;                   // (B, N, C)

    dim3 tgrid(HW / 32, CC / 32, BB);
    dim3 tblk(32, 8);
    k_half<<<tgrid, tblk>>>(img);

    k_sample<<<BB * NN, 128>>>(img, verts, cw, cb, out);
}

// round 5
// speedup vs baseline: 3.2602x; 1.1832x over previous
#include <cuda_runtime.h>
#include <cuda_fp16.h>

// Problem constants (B=2, C=128, H=800, W=640, N=10000)
#define BB 2
#define CC 128
#define HH 800
#define WW 640
#define NN 10000
#define HW (HH * WW)      // 512000

// Scratch: NHWC fp16 hi/lo split of the image.
//  g_h = fp16(x)            -> value path (36 taps)
//  g_l = fp16(x - fp16(x))  -> center/delta path reconstructs x ~ 2^-22 rel
__device__ __half g_h[(size_t)BB * HW * CC];   // 262 MB
__device__ __half g_l[(size_t)BB * HW * CC];   // 262 MB

__device__ __forceinline__ float clampf(float v, float lo, float hi) {
    return fminf(fmaxf(v, lo), hi);
}

// ---------------------------------------------------------------------------
// k_half: transpose (B,C,H,W) fp32 -> (B,H,W,C) fp16 hi + fp16 lo.
// grid = (HW/32, C/32, B), block = (32, 8)
// ---------------------------------------------------------------------------
__global__ void __launch_bounds__(256) k_half(const float* __restrict__ img)
{
    __shared__ float tile[32][33];
    const int b   = blockIdx.z;
    const int c0  = blockIdx.y * 32;
    const int hw0 = blockIdx.x * 32;
    const int tx = threadIdx.x, ty = threadIdx.y;

    const float* __restrict__ src = img + ((size_t)b * CC + c0) * HW + hw0;
    #pragma unroll
    for (int j = 0; j < 32; j += 8)
        tile[ty + j][tx] = src[(size_t)(ty + j) * HW + tx];
    __syncthreads();

    __half* __restrict__ dh = g_h + ((size_t)b * HW + hw0) * CC + c0;
    __half* __restrict__ dl = g_l + ((size_t)b * HW + hw0) * CC + c0;
    #pragma unroll
    for (int j = 0; j < 32; j += 8) {
        const float v = tile[tx][ty + j];            // [c=tx][px=ty+j]
        const __half h = __float2half_rn(v);
        const float r = v - __half2float(h);         // exact in fp32
        const size_t o = (size_t)(ty + j) * CC + tx;
        dh[o] = h;
        dl[o] = __float2half_rn(r);
    }
}

// ---------------------------------------------------------------------------
// k_sample: one block per point (128 threads).
//  A) center 128-ch bilinear sample from hi+lo NHWC (coalesced, ~fp32 exact)
//  B) 18-dot via 8 lanes/output + shfl reduce -> deltas (fp32)
//  C) 9 locations -> tap offsets + weights
//  D) 36 fp16 taps (LDG.64 per 4 channels), mean, float4 coalesced store
// ---------------------------------------------------------------------------
__global__ void __launch_bounds__(128) k_sample(
    const float* __restrict__ verts,
    const float* __restrict__ cw,
    const float* __restrict__ cb,
    float* __restrict__ out)
{
    const int p = blockIdx.x;            // 0 .. B*N-1
    const int b = p / NN;
    const int tid = threadIdx.x;

    __shared__ float sf[CC];
    __shared__ float sd[16];
    __shared__ int   soff[9][4];
    __shared__ float swt[9][4];

    const float vx = verts[p * 2 + 0];
    const float vy = verts[p * 2 + 1];

    const float gx = clampf((vx + 1.0f) * 0.5f * (WW - 1), 0.0f, (float)(WW - 1));
    const float gy = clampf((vy + 1.0f) * 0.5f * (HH - 1), 0.0f, (float)(HH - 1));
    const int x0 = (int)floorf(gx), y0 = (int)floorf(gy);
    const int x1 = min(x0 + 1, WW - 1), y1 = min(y0 + 1, HH - 1);
    const float wx1 = gx - (float)x0, wy1 = gy - (float)y0;
    const float wx0 = 1.0f - wx1, wy0 = 1.0f - wy1;

    const size_t base = (size_t)b * HW * CC;

    // ---- A: center feature from hi+lo, coalesced ----
    {
        const int c = tid;
        const int o00 = (y0 * WW + x0) * CC + c;
        const int o01 = (y0 * WW + x1) * CC + c;
        const int o10 = (y1 * WW + x0) * CC + c;
        const int o11 = (y1 * WW + x1) * CC + c;
        const float f00 = __half2float(g_h[base + o00]) + __half2float(g_l[base + o00]);
        const float f01 = __half2float(g_h[base + o01]) + __half2float(g_l[base + o01]);
        const float f10 = __half2float(g_h[base + o10]) + __half2float(g_l[base + o10]);
        const float f11 = __half2float(g_h[base + o11]) + __half2float(g_l[base + o11]);
        sf[c] = f00 * (wy0 * wx0) + f01 * (wy0 * wx1)
              + f10 * (wy1 * wx0) + f11 * (wy1 * wx1);
    }
    __syncthreads();

    // ---- B: deltas = conv rows 2..17 dot center feature ----
    {
        const int o = tid >> 3;          // 0..15
        const int g = tid & 7;           // 8 lanes per output
        float acc = 0.0f;
        const float* __restrict__ w = cw + (o + 2) * CC + g * 16;
        const float* __restrict__ f = sf + g * 16;
        #pragma unroll
        for (int i = 0; i < 16; i++) acc = fmaf(f[i], w[i], acc);
        acc += __shfl_down_sync(0xffffffffu, acc, 4);
        acc += __shfl_down_sync(0xffffffffu, acc, 2);
        acc += __shfl_down_sync(0xffffffffu, acc, 1);
        if (g == 0) sd[o] = acc + cb[o + 2];
    }
    __syncthreads();

    // ---- C: 9 locations (0 = center, 1..8 = learnt neighbors) ----
    if (tid < 9) {
        float nx = vx, ny = vy;
        if (tid > 0) { nx += sd[2 * tid - 2]; ny += sd[2 * tid - 1]; }
        const float ggx = clampf((nx + 1.0f) * 0.5f * (WW - 1), 0.0f, (float)(WW - 1));
        const float ggy = clampf((ny + 1.0f) * 0.5f * (HH - 1), 0.0f, (float)(HH - 1));
        const int nx0 = (int)floorf(ggx), ny0 = (int)floorf(ggy);
        const int nx1 = min(nx0 + 1, WW - 1), ny1 = min(ny0 + 1, HH - 1);
        const float nwx1 = ggx - (float)nx0, nwy1 = ggy - (float)ny0;
        const float nwx0 = 1.0f - nwx1, nwy0 = 1.0f - nwy1;
        soff[tid][0] = (ny0 * WW + nx0) * CC;
        soff[tid][1] = (ny0 * WW + nx1) * CC;
        soff[tid][2] = (ny1 * WW + nx0) * CC;
        soff[tid][3] = (ny1 * WW + nx1) * CC;
        const float s = 1.0f / 9.0f;
        swt[tid][0] = nwy0 * nwx0 * s;
        swt[tid][1] = nwy0 * nwx1 * s;
        swt[tid][2] = nwy1 * nwx0 * s;
        swt[tid][3] = nwy1 * nwx1 * s;
    }
    __syncthreads();

    // ---- D: 36 fp16 taps; grp = tap j of all 9 locations; lane = 4 channels
    const int lane = tid & 31, grp = tid >> 5;
    const __half* hb = g_h + base + lane * 4;

    float ax = 0.f, ay = 0.f, az = 0.f, aw = 0.f;
    #pragma unroll
    for (int i = 0; i < 9; i++) {
        const int off = soff[i][grp];
        const float w = swt[i][grp];
        const uint2 u = *reinterpret_cast<const uint2*>(hb + off);
        const float2 f0 = __half22float2(*reinterpret_cast<const __half2*>(&u.x));
        const float2 f1 = __half22float2(*reinterpret_cast<const __half2*>(&u.y));
        ax = fmaf(w, f0.x, ax); ay = fmaf(w, f0.y, ay);
        az = fmaf(w, f1.x, az); aw = fmaf(w, f1.y, aw);
    }

    __shared__ float4 red[4][32];
    red[grp][lane] = make_float4(ax, ay, az, aw);
    __syncthreads();

    if (tid < 32) {
        const float4 r0 = red[0][tid], r1 = red[1][tid];
        const float4 r2 = red[2][tid], r3 = red[3][tid];
        float4 o4;
        o4.x = r0.x + r1.x + r2.x + r3.x;
        o4.y = r0.y + r1.y + r2.y + r3.y;
        o4.z = r0.z + r1.z + r2.z + r3.z;
        o4.w = r0.w + r1.w + r2.w + r3.w;
        reinterpret_cast<float4*>(out)[(size_t)p * 32 + tid] = o4;
    }
}

extern "C" void kernel_launch(void* const* d_in, const int* in_sizes, int n_in,
                              void* d_out, int out_size)
{
    const float* img   = (const float*)d_in[0];   // (B, C, H, W)
    const float* verts = (const float*)d_in[1];   // (B, N, 2)
    const float* cw    = (const float*)d_in[2];   // (18, C)
    const float* cb    = (const float*)d_in[3];   // (18,)
    float* out = (float*)d_out;                   // (B, N, C)

    dim3 tgrid(HW / 32, CC / 32, BB);
    dim3 tblk(32, 8);
    k_half<<<tgrid, tblk>>>(img);

    k_sample<<<BB * NN, 128>>>(verts, cw, cb, out);
}

// round 6
// speedup vs baseline: 3.8098x; 1.1686x over previous
#include <cuda_runtime.h>
#include <cuda_fp16.h>

// Problem constants (B=2, C=128, H=800, W=640, N=10000)
#define BB 2
#define CC 128
#define HH 800
#define WW 640
#define NN 10000
#define HW (HH * WW)      // 512000

// Scratch: NHWC fp16 hi/lo split of the image.
//  g_h = fp16(x)            -> value path (36 taps)
//  g_l = fp16(x - fp16(x))  -> center/delta path reconstructs x ~ 2^-22 rel
__device__ __half g_h[(size_t)BB * HW * CC];   // 262 MB
__device__ __half g_l[(size_t)BB * HW * CC];   // 262 MB

__device__ __forceinline__ float clampf(float v, float lo, float hi) {
    return fminf(fmaxf(v, lo), hi);
}

// ---------------------------------------------------------------------------
// k_half: transpose (B,C,H,W) fp32 -> (B,H,W,C) fp16 hi + fp16 lo.
// grid = (HW/32, C/32, B), block = (32, 8). Stores are uint2 (4 ch) wide.
// ---------------------------------------------------------------------------
__global__ void __launch_bounds__(256) k_half(const float* __restrict__ img)
{
    __shared__ float tile[32][33];                 // [c_local][px]
    const int b   = blockIdx.z;
    const int c0  = blockIdx.y * 32;
    const int hw0 = blockIdx.x * 32;
    const int tx = threadIdx.x, ty = threadIdx.y;
    const int tid = ty * 32 + tx;

    const float* __restrict__ src = img + ((size_t)b * CC + c0) * HW + hw0;
    #pragma unroll
    for (int j = 0; j < 32; j += 8)
        tile[ty + j][tx] = src[(size_t)(ty + j) * HW + tx];
    __syncthreads();

    // one uint2 (4 channels) per thread per plane: 32 px x 8 quads = 256
    const int px = tid >> 3;         // 0..31
    const int q  = tid & 7;          // channel quad 0..7
    const float v0 = tile[4 * q + 0][px];
    const float v1 = tile[4 * q + 1][px];
    const float v2 = tile[4 * q + 2][px];
    const float v3 = tile[4 * q + 3][px];

    const __half h0 = __float2half_rn(v0), h1 = __float2half_rn(v1);
    const __half h2 = __float2half_rn(v2), h3 = __float2half_rn(v3);
    const __half r0 = __float2half_rn(v0 - __half2float(h0));
    const __half r1 = __float2half_rn(v1 - __half2float(h1));
    const __half r2 = __float2half_rn(v2 - __half2float(h2));
    const __half r3 = __float2half_rn(v3 - __half2float(h3));

    uint2 uh, ul;
    {
        __half2 a = __halves2half2(h0, h1), c = __halves2half2(h2, h3);
        uh.x = *reinterpret_cast<unsigned int*>(&a);
        uh.y = *reinterpret_cast<unsigned int*>(&c);
        __half2 d = __halves2half2(r0, r1), e = __halves2half2(r2, r3);
        ul.x = *reinterpret_cast<unsigned int*>(&d);
        ul.y = *reinterpret_cast<unsigned int*>(&e);
    }
    const size_t off = (size_t)(b * HW + hw0 + px) * CC + c0 + 4 * q;
    *reinterpret_cast<uint2*>(g_h + off) = uh;
    *reinterpret_cast<uint2*>(g_l + off) = ul;
}

// ---------------------------------------------------------------------------
// k_sample: one block per point (128 threads).
//  A) center sample: warp = tap, lane = 4 ch, LDG.64 hi + LDG.64 lo,
//     weighted partials -> smem reduce (coalesced, ~fp32 exact)
//  B) 18-dot: 8 lanes/output, float4 loads of cw and sf, shfl reduce
//  C) 9 locations -> tap offsets + weights
//  D) 36 fp16 taps (LDG.64 per 4 channels), mean, float4 coalesced store
// ---------------------------------------------------------------------------
__global__ void __launch_bounds__(128) k_sample(
    const float* __restrict__ verts,
    const float* __restrict__ cw,
    const float* __restrict__ cb,
    float* __restrict__ out)
{
    const int p = blockIdx.x;            // 0 .. B*N-1
    const int b = p / NN;
    const int tid = threadIdx.x;
    const int lane = tid & 31, grp = tid >> 5;

    __shared__ float redA[4][CC];
    __shared__ float sf[CC];
    __shared__ float sd[16];
    __shared__ int   soff[9][4];
    __shared__ float swt[9][4];

    const float vx = verts[p * 2 + 0];
    const float vy = verts[p * 2 + 1];

    const float gx = clampf((vx + 1.0f) * 0.5f * (WW - 1), 0.0f, (float)(WW - 1));
    const float gy = clampf((vy + 1.0f) * 0.5f * (HH - 1), 0.0f, (float)(HH - 1));
    const int x0 = (int)floorf(gx), y0 = (int)floorf(gy);
    const int x1 = min(x0 + 1, WW - 1), y1 = min(y0 + 1, HH - 1);
    const float wx1 = gx - (float)x0, wy1 = gy - (float)y0;
    const float wx0 = 1.0f - wx1, wy0 = 1.0f - wy1;

    const size_t base = (size_t)b * HW * CC;

    // ---- A: center feature, warp = tap, lane = 4 channels ----
    {
        const int cx = (grp & 1) ? x1 : x0;
        const int cy = (grp & 2) ? y1 : y0;
        const float wA = ((grp & 1) ? wx1 : wx0) * ((grp & 2) ? wy1 : wy0);
        const size_t o = base + (size_t)(cy * WW + cx) * CC + lane * 4;
        const uint2 uh = *reinterpret_cast<const uint2*>(g_h + o);
        const uint2 ul = *reinterpret_cast<const uint2*>(g_l + o);
        const float2 h0 = __half22float2(*reinterpret_cast<const __half2*>(&uh.x));
        const float2 h1 = __half22float2(*reinterpret_cast<const __half2*>(&uh.y));
        const float2 l0 = __half22float2(*reinterpret_cast<const __half2*>(&ul.x));
        const float2 l1 = __half22float2(*reinterpret_cast<const __half2*>(&ul.y));
        float4 f;
        f.x = (h0.x + l0.x) * wA;
        f.y = (h0.y + l0.y) * wA;
        f.z = (h1.x + l1.x) * wA;
        f.w = (h1.y + l1.y) * wA;
        *reinterpret_cast<float4*>(&redA[grp][lane * 4]) = f;
    }
    __syncthreads();
    sf[tid] = redA[0][tid] + redA[1][tid] + redA[2][tid] + redA[3][tid];
    __syncthreads();

    // ---- B: deltas = conv rows 2..17 dot center feature (float4 loads) ----
    {
        const int o = tid >> 3;          // 0..15
        const int g = tid & 7;           // 8 lanes per output
        const float4* __restrict__ wv =
            reinterpret_cast<const float4*>(cw + (o + 2) * CC + g * 16);
        const float4* __restrict__ fv = reinterpret_cast<const float4*>(sf + g * 16);
        float acc = 0.0f;
        #pragma unroll
        for (int i = 0; i < 4; i++) {
            const float4 w4 = wv[i];
            const float4 f4 = fv[i];
            acc = fmaf(f4.x, w4.x, acc);
            acc = fmaf(f4.y, w4.y, acc);
            acc = fmaf(f4.z, w4.z, acc);
            acc = fmaf(f4.w, w4.w, acc);
        }
        acc += __shfl_down_sync(0xffffffffu, acc, 4);
        acc += __shfl_down_sync(0xffffffffu, acc, 2);
        acc += __shfl_down_sync(0xffffffffu, acc, 1);
        if (g == 0) sd[o] = acc + cb[o + 2];
    }
    __syncthreads();

    // ---- C: 9 locations (0 = center, 1..8 = learnt neighbors) ----
    if (tid < 9) {
        float nx = vx, ny = vy;
        if (tid > 0) { nx += sd[2 * tid - 2]; ny += sd[2 * tid - 1]; }
        const float ggx = clampf((nx + 1.0f) * 0.5f * (WW - 1), 0.0f, (float)(WW - 1));
        const float ggy = clampf((ny + 1.0f) * 0.5f * (HH - 1), 0.0f, (float)(HH - 1));
        const int nx0 = (int)floorf(ggx), ny0 = (int)floorf(ggy);
        const int nx1 = min(nx0 + 1, WW - 1), ny1 = min(ny0 + 1, HH - 1);
        const float nwx1 = ggx - (float)nx0, nwy1 = ggy - (float)ny0;
        const float nwx0 = 1.0f - nwx1, nwy0 = 1.0f - nwy1;
        soff[tid][0] = (ny0 * WW + nx0) * CC;
        soff[tid][1] = (ny0 * WW + nx1) * CC;
        soff[tid][2] = (ny1 * WW + nx0) * CC;
        soff[tid][3] = (ny1 * WW + nx1) * CC;
        const float s = 1.0f / 9.0f;
        swt[tid][0] = nwy0 * nwx0 * s;
        swt[tid][1] = nwy0 * nwx1 * s;
        swt[tid][2] = nwy1 * nwx0 * s;
        swt[tid][3] = nwy1 * nwx1 * s;
    }
    __syncthreads();

    // ---- D: 36 fp16 taps; grp = tap j of all 9 locations; lane = 4 channels
    const __half* hb = g_h + base + lane * 4;

    float ax = 0.f, ay = 0.f, az = 0.f, aw = 0.f;
    #pragma unroll
    for (int i = 0; i < 9; i++) {
        const int off = soff[i][grp];
        const float w = swt[i][grp];
        const uint2 u = *reinterpret_cast<const uint2*>(hb + off);
        const float2 f0 = __half22float2(*reinterpret_cast<const __half2*>(&u.x));
        const float2 f1 = __half22float2(*reinterpret_cast<const __half2*>(&u.y));
        ax = fmaf(w, f0.x, ax); ay = fmaf(w, f0.y, ay);
        az = fmaf(w, f1.x, az); aw = fmaf(w, f1.y, aw);
    }

    __shared__ float4 red[4][32];
    red[grp][lane] = make_float4(ax, ay, az, aw);
    __syncthreads();

    if (tid < 32) {
        const float4 r0 = red[0][tid], r1 = red[1][tid];
        const float4 r2 = red[2][tid], r3 = red[3][tid];
        float4 o4;
        o4.x = r0.x + r1.x + r2.x + r3.x;
        o4.y = r0.y + r1.y + r2.y + r3.y;
        o4.z = r0.z + r1.z + r2.z + r3.z;
        o4.w = r0.w + r1.w + r2.w + r3.w;
        reinterpret_cast<float4*>(out)[(size_t)p * 32 + tid] = o4;
    }
}

extern "C" void kernel_launch(void* const* d_in, const int* in_sizes, int n_in,
                              void* d_out, int out_size)
{
    const float* img   = (const float*)d_in[0];   // (B, C, H, W)
    const float* verts = (const float*)d_in[1];   // (B, N, 2)
    const float* cw    = (const float*)d_in[2];   // (18, C)
    const float* cb    = (const float*)d_in[3];   // (18,)
    float* out = (float*)d_out;                   // (B, N, C)

    dim3 tgrid(HW / 32, CC / 32, BB);
    dim3 tblk(32, 8);
    k_half<<<tgrid, tblk>>>(img);

    k_sample<<<BB * NN, 128>>>(verts, cw, cb, out);
}